// round 3
// baseline (speedup 1.0000x reference)
#include <cuda_runtime.h>
#include <math.h>

#define DD   128
#define NU   40000
#define NTOT 80000
#define EMP  640000
#define EUI  1600000
#define BSZ  8192

// ------------------------- static device scratch (~222MB) -------------------
__device__ float d_h[2 * NU * DD];       // h_u, h_i
__device__ float d_z[2 * NU * DD];       // z for 2 metapaths (reused per side/layer)
__device__ float d_x[2 * NTOT * DD];     // lightgcn ping-pong
__device__ float d_emb[2 * NU * DD];     // user_emb_pre, item_emb_pre
__device__ float d_rout[4 * NU];
__device__ float d_rin[4 * NU];
__device__ int   d_deg[8 * NU];          // [0,4NU)=outdeg per path, [4NU,8NU)=indeg
__device__ int   d_off[4 * (NU + 1)];
__device__ int   d_cur[4 * NU];
__device__ int   d_csr[4 * EMP];
__device__ int   d_cntui[NTOT];
__device__ float d_dinv[NTOT];
__device__ int   d_offui[NTOT + 1];
__device__ int   d_curui[NTOT];
__device__ int   d_csrui[EUI];
__device__ float d_att[2 * DD];
__device__ float d_beta[2];
__device__ float d_n1[BSZ * DD];
__device__ float d_n2[BSZ * DD];
__device__ float d_alls[BSZ];
__device__ float d_dpos[BSZ];
__device__ float d_ssl[1];

// ------------------------- small utilities ----------------------------------
__global__ void k_zero_i(int* p, int n) {
    int i = blockIdx.x * blockDim.x + threadIdx.x;
    if (i < n) p[i] = 0;
}
__global__ void k_zero_f(float* p, int n) {
    int i = blockIdx.x * blockDim.x + threadIdx.x;
    if (i < n) p[i] = 0.f;
}
__global__ void k_count(const int* __restrict__ ids, int n, int* __restrict__ cnt) {
    int i = blockIdx.x * blockDim.x + threadIdx.x;
    if (i < n) atomicAdd(&cnt[ids[i]], 1);
}
__global__ void k_rsq(const int* __restrict__ deg, float* __restrict__ r, int n) {
    int i = blockIdx.x * blockDim.x + threadIdx.x;
    if (i < n) r[i] = rsqrtf(fmaxf((float)deg[i], 1.f));
}
__global__ void k_dinvk(const int* __restrict__ cnt, float* __restrict__ dinv, int n) {
    int i = blockIdx.x * blockDim.x + threadIdx.x;
    if (i < n) {
        int c = cnt[i];
        dinv[i] = (c > 0) ? rsqrtf((float)c) : 0.f;
    }
}
// single-block exclusive scan; also initializes cur = off
__global__ void k_scan(const int* __restrict__ cnt, int* __restrict__ off,
                       int* __restrict__ cur, int n) {
    __shared__ int part[1024];
    int t = threadIdx.x;
    int chunk = (n + 1023) >> 10;
    int base = t * chunk;
    int s = 0;
    for (int i = 0; i < chunk; i++) {
        int g = base + i;
        if (g < n) s += cnt[g];
    }
    part[t] = s;
    __syncthreads();
    for (int o = 1; o < 1024; o <<= 1) {
        int v = (t >= o) ? part[t - o] : 0;
        __syncthreads();
        part[t] += v;
        __syncthreads();
    }
    int run = (t == 0) ? 0 : part[t - 1];
    for (int i = 0; i < chunk; i++) {
        int g = base + i;
        if (g < n) { off[g] = run; cur[g] = run; run += cnt[g]; }
    }
    if (t == 0) off[n] = part[1023];
}
__global__ void k_fill(const int* __restrict__ key, const int* __restrict__ val,
                       int n, int* __restrict__ cur, int* __restrict__ csr) {
    int i = blockIdx.x * blockDim.x + threadIdx.x;
    if (i < n) {
        int slot = atomicAdd(&cur[key[i]], 1);
        csr[slot] = val[i];
    }
}

// ------------------------- pull-style graph conv ----------------------------
// z[v] = rin[v] * sum_{s in csr[off[v]..off[v+1])} h[s] * rout[s]
__global__ void __launch_bounds__(256) k_pull(
        const float* __restrict__ h, const float* __restrict__ rout,
        const float* __restrict__ rin, const int* __restrict__ off,
        const int* __restrict__ csr, float* __restrict__ z, int n)
{
    int gid = blockIdx.x * blockDim.x + threadIdx.x;
    int v = gid >> 5;
    if (v >= n) return;
    int lane = (gid & 31) << 2;
    int j = off[v], jend = off[v + 1];
    float ax = 0.f, ay = 0.f, az = 0.f, aw = 0.f;
    for (; j + 4 <= jend; j += 4) {
        int s0 = csr[j], s1 = csr[j + 1], s2 = csr[j + 2], s3 = csr[j + 3];
        float r0 = __ldg(rout + s0), r1 = __ldg(rout + s1);
        float r2 = __ldg(rout + s2), r3 = __ldg(rout + s3);
        float4 h0 = *(const float4*)(h + (size_t)s0 * DD + lane);
        float4 h1 = *(const float4*)(h + (size_t)s1 * DD + lane);
        float4 h2 = *(const float4*)(h + (size_t)s2 * DD + lane);
        float4 h3 = *(const float4*)(h + (size_t)s3 * DD + lane);
        ax += h0.x * r0 + h1.x * r1 + h2.x * r2 + h3.x * r3;
        ay += h0.y * r0 + h1.y * r1 + h2.y * r2 + h3.y * r3;
        az += h0.z * r0 + h1.z * r1 + h2.z * r2 + h3.z * r3;
        aw += h0.w * r0 + h1.w * r1 + h2.w * r2 + h3.w * r3;
    }
    for (; j < jend; j++) {
        int s = csr[j];
        float r = __ldg(rout + s);
        float4 hv = *(const float4*)(h + (size_t)s * DD + lane);
        ax = fmaf(hv.x, r, ax); ay = fmaf(hv.y, r, ay);
        az = fmaf(hv.z, r, az); aw = fmaf(hv.w, r, aw);
    }
    float ri = rin[v];
    float4 o;
    o.x = ax * ri; o.y = ay * ri; o.z = az * ri; o.w = aw * ri;
    *(float4*)(z + (size_t)v * DD + lane) = o;
}

// ------------- semantic attention: colsum of tanh(Z @ W1 + b1) --------------
__global__ void __launch_bounds__(256) k_att(
        const float* __restrict__ z, const float* __restrict__ W1,
        const float* __restrict__ b1, float* __restrict__ attsum, int n)
{
    extern __shared__ float sm[];
    float* Ws = sm;            // 128*128
    float* Zs = sm + 16384;    // 8 warps * 4 rows * 128
    __shared__ float sred[DD];
    int t = threadIdx.x;
    for (int i = t; i < 4096; i += 256)
        ((float4*)Ws)[i] = ((const float4*)W1)[i];
    if (t < DD) sred[t] = 0.f;
    __syncthreads();
    int warp = t >> 5, lane = t & 31;
    float4 b4 = ((const float4*)b1)[lane];
    float cs0 = 0.f, cs1 = 0.f, cs2 = 0.f, cs3 = 0.f;
    float* zr = Zs + warp * 512;
    for (int base = (blockIdx.x * 8 + warp) * 4; base < n; base += gridDim.x * 32) {
        const float4* src = (const float4*)(z + (size_t)base * DD);
        for (int i = lane; i < 128; i += 32)
            ((float4*)zr)[i] = src[i];
        __syncwarp();
        float acc[4][4] = {};
#pragma unroll 4
        for (int k = 0; k < DD; k++) {
            float4 w = *(const float4*)(Ws + k * DD + lane * 4);
            float zv[4];
            zv[0] = zr[k]; zv[1] = zr[DD + k]; zv[2] = zr[2 * DD + k]; zv[3] = zr[3 * DD + k];
#pragma unroll
            for (int r = 0; r < 4; r++) {
                acc[r][0] = fmaf(zv[r], w.x, acc[r][0]);
                acc[r][1] = fmaf(zv[r], w.y, acc[r][1]);
                acc[r][2] = fmaf(zv[r], w.z, acc[r][2]);
                acc[r][3] = fmaf(zv[r], w.w, acc[r][3]);
            }
        }
#pragma unroll
        for (int r = 0; r < 4; r++) {
            cs0 += tanhf(acc[r][0] + b4.x);
            cs1 += tanhf(acc[r][1] + b4.y);
            cs2 += tanhf(acc[r][2] + b4.z);
            cs3 += tanhf(acc[r][3] + b4.w);
        }
        __syncwarp();
    }
    atomicAdd(&sred[lane * 4 + 0], cs0);
    atomicAdd(&sred[lane * 4 + 1], cs1);
    atomicAdd(&sred[lane * 4 + 2], cs2);
    atomicAdd(&sred[lane * 4 + 3], cs3);
    __syncthreads();
    if (t < DD) atomicAdd(&attsum[t], sred[t]);
}

__global__ void k_beta(const float* __restrict__ W2, int n) {
    float w0 = 0.f, w1 = 0.f;
    for (int k = 0; k < DD; k++) {
        w0 += d_att[k] * W2[k];
        w1 += d_att[DD + k] * W2[k];
    }
    float inv = 1.f / (float)n;
    w0 *= inv; w1 *= inv;
    float m = fmaxf(w0, w1);
    float e0 = expf(w0 - m), e1 = expf(w1 - m);
    float den = 1.f / (e0 + e1);
    d_beta[0] = e0 * den;
    d_beta[1] = e1 * den;
}

__global__ void k_combine(const float* __restrict__ z, float* __restrict__ h, int n) {
    int i = blockIdx.x * blockDim.x + threadIdx.x;
    if (i < n) h[i] = d_beta[0] * z[i] + d_beta[1] * z[i + NU * DD];
}

__global__ void k_emb(const float* __restrict__ xf, int n) {
    int i = blockIdx.x * blockDim.x + threadIdx.x;
    if (i < n) {
        d_emb[i]           = 0.5f * (d_h[i] + xf[i]);
        d_emb[NU * DD + i] = 0.5f * (d_h[NU * DD + i] + xf[NU * DD + i]);
    }
}

// ------------------------- SSL ----------------------------------------------
__global__ void __launch_bounds__(256) k_norm(
        const float* __restrict__ e1b, const float* __restrict__ e2b,
        const int* __restrict__ idx)
{
    int gid = blockIdx.x * blockDim.x + threadIdx.x;
    int r = gid >> 5;
    if (r >= BSZ) return;
    int lane = gid & 31;
    int row = idx[r];
    float4 a = *(const float4*)(e1b + (size_t)row * DD + lane * 4);
    float4 b = *(const float4*)(e2b + (size_t)row * DD + lane * 4);
    float s11 = a.x * a.x + a.y * a.y + a.z * a.z + a.w * a.w;
    float s22 = b.x * b.x + b.y * b.y + b.z * b.z + b.w * b.w;
    float s12 = a.x * b.x + a.y * b.y + a.z * b.z + a.w * b.w;
    for (int o = 16; o; o >>= 1) {
        s11 += __shfl_xor_sync(0xffffffffu, s11, o);
        s22 += __shfl_xor_sync(0xffffffffu, s22, o);
        s12 += __shfl_xor_sync(0xffffffffu, s12, o);
    }
    float i1 = 1.f / fmaxf(sqrtf(s11), 1e-12f);
    float i2 = 1.f / fmaxf(sqrtf(s22), 1e-12f);
    if (lane == 0) d_dpos[r] = s12 * i1 * i2;
    float4 na, nb;
    na.x = a.x * i1; na.y = a.y * i1; na.z = a.z * i1; na.w = a.w * i1;
    nb.x = b.x * i2; nb.y = b.y * i2; nb.z = b.z * i2; nb.w = b.w * i2;
    *(float4*)(d_n1 + (size_t)r * DD + lane * 4) = na;
    *(float4*)(d_n2 + (size_t)r * DD + lane * 4) = nb;
}

__device__ __forceinline__ float fast_exp(float x) {
    // exp(x) for x in [-2.1, 2.1]: exp2 split + degree-6 poly for 2^f, |f|<=0.5
    float y = x * 1.4426950408889634f;
    float nf = rintf(y);
    float f = y - nf;
    float p = 1.5403530e-4f;
    p = fmaf(p, f, 1.3333558e-3f);
    p = fmaf(p, f, 9.6181291e-3f);
    p = fmaf(p, f, 5.5504109e-2f);
    p = fmaf(p, f, 2.4022651e-1f);
    p = fmaf(p, f, 6.9314718e-1f);
    p = fmaf(p, f, 1.0f);
    return p * __int_as_float(((int)nf + 127) << 23);
}

// S = n1 @ n2^T (8192x8192, K=128); alls[i] += sum_j exp(2*S_ij)
// 128x128 block tile, 256 threads, 8x8 micro-tile, K-slab 8.
__global__ void __launch_bounds__(256) k_sslgemm()
{
    __shared__ float As[8 * 132];
    __shared__ float Bs[8 * 132];
    __shared__ float sred[128];
    int t = threadIdx.x;
    int tx = t & 15, ty = t >> 4;
    int rowA0 = blockIdx.y * 128;
    int colB0 = blockIdx.x * 128;
    if (t < 128) sred[t] = 0.f;
    float acc[8][8] = {};
    int lr = t >> 1, part = t & 1;
    for (int kk = 0; kk < DD; kk += 8) {
        float4 av = *(const float4*)(d_n1 + (size_t)(rowA0 + lr) * DD + kk + part * 4);
        float4 bv = *(const float4*)(d_n2 + (size_t)(colB0 + lr) * DD + kk + part * 4);
        __syncthreads();
        As[(part * 4 + 0) * 132 + lr] = av.x;
        As[(part * 4 + 1) * 132 + lr] = av.y;
        As[(part * 4 + 2) * 132 + lr] = av.z;
        As[(part * 4 + 3) * 132 + lr] = av.w;
        Bs[(part * 4 + 0) * 132 + lr] = bv.x;
        Bs[(part * 4 + 1) * 132 + lr] = bv.y;
        Bs[(part * 4 + 2) * 132 + lr] = bv.z;
        Bs[(part * 4 + 3) * 132 + lr] = bv.w;
        __syncthreads();
#pragma unroll
        for (int k = 0; k < 8; k++) {
            float a[8], b[8];
            *(float4*)(a)     = *(const float4*)(As + k * 132 + ty * 8);
            *(float4*)(a + 4) = *(const float4*)(As + k * 132 + ty * 8 + 4);
            *(float4*)(b)     = *(const float4*)(Bs + k * 132 + tx * 8);
            *(float4*)(b + 4) = *(const float4*)(Bs + k * 132 + tx * 8 + 4);
#pragma unroll
            for (int i = 0; i < 8; i++)
#pragma unroll
                for (int j = 0; j < 8; j++)
                    acc[i][j] = fmaf(a[i], b[j], acc[i][j]);
        }
    }
#pragma unroll
    for (int i = 0; i < 8; i++) {
        float rs = 0.f;
#pragma unroll
        for (int j = 0; j < 8; j++)
            rs += fast_exp(acc[i][j] * 2.f);
        atomicAdd(&sred[ty * 8 + i], rs);
    }
    __syncthreads();
    if (t < 128) atomicAdd(&d_alls[rowA0 + t], sred[t]);
}

__global__ void k_sslreduce(float scale) {
    __shared__ float sp[256];
    int t = threadIdx.x;
    float s = 0.f;
    for (int i = t; i < BSZ; i += 256)
        s += logf(d_alls[i]) - 2.f * d_dpos[i];
    sp[t] = s;
    __syncthreads();
    for (int o = 128; o; o >>= 1) {
        if (t < o) sp[t] += sp[t + o];
        __syncthreads();
    }
    if (t == 0) atomicAdd(&d_ssl[0], sp[0] * scale);
}

__global__ void k_writeloss(float* dst) { *dst = d_ssl[0]; }

// ------------- final: out = LN(relu(emb[idx] @ W + b)) ----------------------
__global__ void __launch_bounds__(256) k_final(
        const float* __restrict__ embb, const int* __restrict__ idx,
        const float* __restrict__ W, const float* __restrict__ bias,
        const float* __restrict__ lng, const float* __restrict__ lnb,
        float* __restrict__ outb)
{
    extern __shared__ float sm[];
    float* Ws = sm;
    float* Zs = sm + 16384;
    int t = threadIdx.x;
    for (int i = t; i < 4096; i += 256)
        ((float4*)Ws)[i] = ((const float4*)W)[i];
    __syncthreads();
    int warp = t >> 5, lane = t & 31;
    int base = (blockIdx.x * 8 + warp) * 4;
    float* zr = Zs + warp * 512;
    for (int i = lane; i < 128; i += 32) {
        int r = i >> 5, c = i & 31;
        ((float4*)zr)[i] = ((const float4*)(embb + (size_t)idx[base + r] * DD))[c];
    }
    __syncwarp();
    float4 bb = ((const float4*)bias)[lane];
    float acc[4][4];
#pragma unroll
    for (int r = 0; r < 4; r++) {
        acc[r][0] = bb.x; acc[r][1] = bb.y; acc[r][2] = bb.z; acc[r][3] = bb.w;
    }
#pragma unroll 4
    for (int k = 0; k < DD; k++) {
        float4 w = *(const float4*)(Ws + k * DD + lane * 4);
        float zv[4];
        zv[0] = zr[k]; zv[1] = zr[DD + k]; zv[2] = zr[2 * DD + k]; zv[3] = zr[3 * DD + k];
#pragma unroll
        for (int r = 0; r < 4; r++) {
            acc[r][0] = fmaf(zv[r], w.x, acc[r][0]);
            acc[r][1] = fmaf(zv[r], w.y, acc[r][1]);
            acc[r][2] = fmaf(zv[r], w.z, acc[r][2]);
            acc[r][3] = fmaf(zv[r], w.w, acc[r][3]);
        }
    }
    float4 g4 = ((const float4*)lng)[lane];
    float4 lb4 = ((const float4*)lnb)[lane];
#pragma unroll
    for (int r = 0; r < 4; r++) {
        float v0 = fmaxf(acc[r][0], 0.f), v1 = fmaxf(acc[r][1], 0.f);
        float v2 = fmaxf(acc[r][2], 0.f), v3 = fmaxf(acc[r][3], 0.f);
        float s = v0 + v1 + v2 + v3;
        for (int o = 16; o; o >>= 1) s += __shfl_xor_sync(0xffffffffu, s, o);
        float mu = s * (1.f / 128.f);
        float w0 = v0 - mu, w1 = v1 - mu, w2 = v2 - mu, w3 = v3 - mu;
        float q = w0 * w0 + w1 * w1 + w2 * w2 + w3 * w3;
        for (int o = 16; o; o >>= 1) q += __shfl_xor_sync(0xffffffffu, q, o);
        float inv = rsqrtf(q * (1.f / 128.f) + 1e-5f);
        float4 ov;
        ov.x = w0 * inv * g4.x + lb4.x;
        ov.y = w1 * inv * g4.y + lb4.y;
        ov.z = w2 * inv * g4.z + lb4.z;
        ov.w = w3 * inv * g4.w + lb4.w;
        *(float4*)(outb + (size_t)(base + r) * DD + lane * 4) = ov;
    }
}

// ------------------------- host orchestration -------------------------------
extern "C" void kernel_launch(void* const* d_in, const int* in_sizes, int n_in,
                              void* d_out, int out_size)
{
    const float* feat_user = (const float*)d_in[0];
    const float* feat_item = (const float*)d_in[1];
    const float* u_W1 = (const float*)d_in[2];
    const float* u_b1 = (const float*)d_in[3];
    const float* u_W2 = (const float*)d_in[4];
    const float* i_W1 = (const float*)d_in[5];
    const float* i_b1 = (const float*)d_in[6];
    const float* i_W2 = (const float*)d_in[7];
    const float* user_W = (const float*)d_in[8];
    const float* user_b = (const float*)d_in[9];
    const float* item_W = (const float*)d_in[10];
    const float* item_b = (const float*)d_in[11];
    const float* ln_g = (const float*)d_in[12];
    const float* ln_b = (const float*)d_in[13];
    const int* mpsrc[4] = {(const int*)d_in[14], (const int*)d_in[16],
                           (const int*)d_in[18], (const int*)d_in[20]};
    const int* mpdst[4] = {(const int*)d_in[15], (const int*)d_in[17],
                           (const int*)d_in[19], (const int*)d_in[21]};
    const int* ui_row = (const int*)d_in[22];
    const int* ui_col = (const int*)d_in[23];
    const int* user_idx = (const int*)d_in[24];
    const int* item_idx = (const int*)d_in[25];
    const int* neg_idx = (const int*)d_in[26];
    float* out = (float*)d_out;

    float *p_h, *p_z, *p_x, *p_emb, *p_rout, *p_rin, *p_dinv, *p_att, *p_alls, *p_ssl;
    int *p_deg, *p_off, *p_cur, *p_csr, *p_cntui, *p_offui, *p_curui, *p_csrui;
    cudaGetSymbolAddress((void**)&p_h, d_h);
    cudaGetSymbolAddress((void**)&p_z, d_z);
    cudaGetSymbolAddress((void**)&p_x, d_x);
    cudaGetSymbolAddress((void**)&p_emb, d_emb);
    cudaGetSymbolAddress((void**)&p_rout, d_rout);
    cudaGetSymbolAddress((void**)&p_rin, d_rin);
    cudaGetSymbolAddress((void**)&p_dinv, d_dinv);
    cudaGetSymbolAddress((void**)&p_att, d_att);
    cudaGetSymbolAddress((void**)&p_alls, d_alls);
    cudaGetSymbolAddress((void**)&p_ssl, d_ssl);
    cudaGetSymbolAddress((void**)&p_deg, d_deg);
    cudaGetSymbolAddress((void**)&p_off, d_off);
    cudaGetSymbolAddress((void**)&p_cur, d_cur);
    cudaGetSymbolAddress((void**)&p_csr, d_csr);
    cudaGetSymbolAddress((void**)&p_cntui, d_cntui);
    cudaGetSymbolAddress((void**)&p_offui, d_offui);
    cudaGetSymbolAddress((void**)&p_curui, d_curui);
    cudaGetSymbolAddress((void**)&p_csrui, d_csrui);

    cudaFuncSetAttribute(k_att, cudaFuncAttributeMaxDynamicSharedMemorySize, 81920);
    cudaFuncSetAttribute(k_final, cudaFuncAttributeMaxDynamicSharedMemorySize, 81920);

    const int T = 256;

    // ---- degrees + CSR build ----
    k_zero_i<<<(8 * NU + T - 1) / T, T>>>(p_deg, 8 * NU);
    k_zero_i<<<(NTOT + T - 1) / T, T>>>(p_cntui, NTOT);
    k_zero_f<<<1, 1>>>(p_ssl, 1);
    for (int p = 0; p < 4; p++) {
        k_count<<<(EMP + T - 1) / T, T>>>(mpsrc[p], EMP, p_deg + p * NU);
        k_count<<<(EMP + T - 1) / T, T>>>(mpdst[p], EMP, p_deg + (4 + p) * NU);
    }
    k_count<<<(EUI + T - 1) / T, T>>>(ui_row, EUI, p_cntui);
    k_rsq<<<(4 * NU + T - 1) / T, T>>>(p_deg, p_rout, 4 * NU);
    k_rsq<<<(4 * NU + T - 1) / T, T>>>(p_deg + 4 * NU, p_rin, 4 * NU);
    k_dinvk<<<(NTOT + T - 1) / T, T>>>(p_cntui, p_dinv, NTOT);
    for (int p = 0; p < 4; p++) {
        k_scan<<<1, 1024>>>(p_deg + (4 + p) * NU, p_off + p * (NU + 1), p_cur + p * NU, NU);
        k_fill<<<(EMP + T - 1) / T, T>>>(mpdst[p], mpsrc[p], EMP, p_cur + p * NU, p_csr + p * EMP);
    }
    k_scan<<<1, 1024>>>(p_cntui, p_offui, p_curui, NTOT);
    k_fill<<<(EUI + T - 1) / T, T>>>(ui_row, ui_col, EUI, p_curui, p_csrui);

    // ---- HAN (both sides) ----
    for (int side = 0; side < 2; side++) {
        const float* feat = side ? feat_item : feat_user;
        const float* W1 = side ? i_W1 : u_W1;
        const float* b1 = side ? i_b1 : u_b1;
        const float* W2 = side ? i_W2 : u_W2;
        float* h = p_h + (size_t)side * NU * DD;
        int p0 = side * 2, p1 = side * 2 + 1;
        for (int layer = 0; layer < 3; layer++) {
            const float* hin = layer ? h : feat;
            k_pull<<<(NU * 32) / T, T>>>(hin, p_rout + p0 * NU, p_rin + p0 * NU,
                                         p_off + p0 * (NU + 1), p_csr + (size_t)p0 * EMP,
                                         p_z, NU);
            k_pull<<<(NU * 32) / T, T>>>(hin, p_rout + p1 * NU, p_rin + p1 * NU,
                                         p_off + p1 * (NU + 1), p_csr + (size_t)p1 * EMP,
                                         p_z + (size_t)NU * DD, NU);
            k_zero_f<<<1, 256>>>(p_att, 2 * DD);
            k_att<<<148, 256, 81920>>>(p_z, W1, b1, p_att, NU);
            k_att<<<148, 256, 81920>>>(p_z + (size_t)NU * DD, W1, b1, p_att + DD, NU);
            k_beta<<<1, 1>>>(W2, NU);
            k_combine<<<(NU * DD + T - 1) / T, T>>>(p_z, h, NU * DD);
        }
    }

    // ---- LightGCN (3 hops) ----
    cudaMemcpyAsync(p_x, feat_user, (size_t)NU * DD * sizeof(float),
                    cudaMemcpyDeviceToDevice);
    cudaMemcpyAsync(p_x + (size_t)NU * DD, feat_item, (size_t)NU * DD * sizeof(float),
                    cudaMemcpyDeviceToDevice);
    float* x0 = p_x;
    float* x1 = p_x + (size_t)NTOT * DD;
    k_pull<<<(NTOT * 32) / T, T>>>(x0, p_dinv, p_dinv, p_offui, p_csrui, x1, NTOT);
    k_pull<<<(NTOT * 32) / T, T>>>(x1, p_dinv, p_dinv, p_offui, p_csrui, x0, NTOT);
    k_pull<<<(NTOT * 32) / T, T>>>(x0, p_dinv, p_dinv, p_offui, p_csrui, x1, NTOT);
    float* xf = x1;

    // ---- combine embeddings ----
    k_emb<<<(NU * DD + T - 1) / T, T>>>(xf, NU * DD);

    // ---- SSL (user then item) ----
    dim3 gg(BSZ / 128, BSZ / 128);
    k_norm<<<(BSZ * 32) / T, T>>>(xf, p_emb, user_idx);
    k_zero_f<<<(BSZ + T - 1) / T, T>>>(p_alls, BSZ);
    k_sslgemm<<<gg, 256>>>();
    k_sslreduce<<<1, 256>>>(0.4f / (float)BSZ);
    k_norm<<<(BSZ * 32) / T, T>>>(xf + (size_t)NU * DD, p_emb + (size_t)NU * DD, item_idx);
    k_zero_f<<<(BSZ + T - 1) / T, T>>>(p_alls, BSZ);
    k_sslgemm<<<gg, 256>>>();
    k_sslreduce<<<1, 256>>>(0.4f / (float)BSZ);
    k_writeloss<<<1, 1>>>(out + (size_t)3 * BSZ * DD);

    // ---- final gather + GEMM + relu + layernorm ----
    k_final<<<BSZ / 32, 256, 81920>>>(p_emb, user_idx, user_W, user_b, ln_g, ln_b, out);
    k_final<<<BSZ / 32, 256, 81920>>>(p_emb + (size_t)NU * DD, item_idx, item_W, item_b,
                                      ln_g, ln_b, out + (size_t)BSZ * DD);
    k_final<<<BSZ / 32, 256, 81920>>>(p_emb + (size_t)NU * DD, neg_idx, item_W, item_b,
                                      ln_g, ln_b, out + (size_t)2 * BSZ * DD);
}

// round 10
// speedup vs baseline: 1.8339x; 1.8339x over previous
#include <cuda_runtime.h>
#include <cuda_bf16.h>
#include <stdint.h>
#include <math.h>

#define DD   128
#define NU   40000
#define NTOT 80000
#define EMP  640000
#define EUI  1600000
#define BSZ  8192
#define ATT_BLOCKS 313
#define SST 136

// ------------------------- static device scratch ----------------------------
__device__ float d_h[2 * NU * DD];
__device__ float d_z[2 * NU * DD];
__device__ __nv_bfloat16 d_zh[2 * NU * DD];
__device__ __nv_bfloat16 d_w1h[DD * DD];
__device__ float d_x[2 * NTOT * DD];
__device__ float d_emb[2 * NU * DD];
__device__ float d_rout[4 * NU];
__device__ float d_rin[4 * NU];
__device__ int   d_deg[8 * NU];
__device__ int   d_off[4 * (NU + 1)];
__device__ int   d_cur[4 * NU];
__device__ int   d_csr[4 * EMP];
__device__ int   d_cntui[NTOT];
__device__ float d_dinv[NTOT];
__device__ int   d_offui[NTOT + 1];
__device__ int   d_curui[NTOT];
__device__ int   d_csrui[EUI];
__device__ float d_att[2 * DD];
__device__ float d_beta[2];
__device__ __nv_bfloat16 d_n1h[2 * BSZ * DD];
__device__ __nv_bfloat16 d_n2h[2 * BSZ * DD];
__device__ float d_alls[2 * BSZ];
__device__ float d_dpos[2 * BSZ];
__device__ float d_ssl[1];

// ------------------------- mma helpers --------------------------------------
__device__ __forceinline__ uint32_t smem_u32(const void* p) {
    return (uint32_t)__cvta_generic_to_shared(const_cast<void*>(p));
}
__device__ __forceinline__ void ldmx4(uint32_t* r, uint32_t a) {
    asm volatile("ldmatrix.sync.aligned.m8n8.x4.shared.b16 {%0,%1,%2,%3}, [%4];"
        : "=r"(r[0]), "=r"(r[1]), "=r"(r[2]), "=r"(r[3]) : "r"(a));
}
__device__ __forceinline__ void mma_bf16(float* c, const uint32_t* a, const uint32_t* b) {
    asm volatile(
        "mma.sync.aligned.m16n8k16.row.col.f32.bf16.bf16.f32 "
        "{%0,%1,%2,%3},{%4,%5,%6,%7},{%8,%9},{%0,%1,%2,%3};"
        : "+f"(c[0]), "+f"(c[1]), "+f"(c[2]), "+f"(c[3])
        : "r"(a[0]), "r"(a[1]), "r"(a[2]), "r"(a[3]), "r"(b[0]), "r"(b[1]));
}

// ------------------------- small utilities ----------------------------------
__global__ void k_zero_i(int* p, int n) {
    int i = blockIdx.x * blockDim.x + threadIdx.x;
    if (i < n) p[i] = 0;
}
__global__ void k_zero_f(float* p, int n) {
    int i = blockIdx.x * blockDim.x + threadIdx.x;
    if (i < n) p[i] = 0.f;
}
__global__ void k_count(const int* __restrict__ ids, int n, int* __restrict__ cnt) {
    int i = blockIdx.x * blockDim.x + threadIdx.x;
    if (i < n) atomicAdd(&cnt[ids[i]], 1);
}
__global__ void k_rsq(const int* __restrict__ deg, float* __restrict__ r, int n) {
    int i = blockIdx.x * blockDim.x + threadIdx.x;
    if (i < n) r[i] = rsqrtf(fmaxf((float)deg[i], 1.f));
}
__global__ void k_dinvk(const int* __restrict__ cnt, float* __restrict__ dinv, int n) {
    int i = blockIdx.x * blockDim.x + threadIdx.x;
    if (i < n) {
        int c = cnt[i];
        dinv[i] = (c > 0) ? rsqrtf((float)c) : 0.f;
    }
}
__global__ void k_scan(const int* __restrict__ cnt, int* __restrict__ off,
                       int* __restrict__ cur, int n) {
    __shared__ int part[1024];
    int t = threadIdx.x;
    int chunk = (n + 1023) >> 10;
    int base = t * chunk;
    int s = 0;
    for (int i = 0; i < chunk; i++) {
        int g = base + i;
        if (g < n) s += cnt[g];
    }
    part[t] = s;
    __syncthreads();
    for (int o = 1; o < 1024; o <<= 1) {
        int v = (t >= o) ? part[t - o] : 0;
        __syncthreads();
        part[t] += v;
        __syncthreads();
    }
    int run = (t == 0) ? 0 : part[t - 1];
    for (int i = 0; i < chunk; i++) {
        int g = base + i;
        if (g < n) { off[g] = run; cur[g] = run; run += cnt[g]; }
    }
    if (t == 0) off[n] = part[1023];
}
__global__ void k_fill(const int* __restrict__ key, const int* __restrict__ val,
                       int n, int* __restrict__ cur, int* __restrict__ csr) {
    int i = blockIdx.x * blockDim.x + threadIdx.x;
    if (i < n) {
        int slot = atomicAdd(&cur[key[i]], 1);
        csr[slot] = val[i];
    }
}
__global__ void k_cvtW(const float* __restrict__ W, __nv_bfloat16* __restrict__ Wh) {
    int i = blockIdx.x * blockDim.x + threadIdx.x;
    if (i < DD * DD) {
        int k = i >> 7, nn = i & 127;
        Wh[nn * DD + k] = __float2bfloat16(W[i]);  // [n][k]
    }
}

// ------------------------- pull-style graph conv ----------------------------
__global__ void __launch_bounds__(256) k_pull(
        const float* __restrict__ h, const float* __restrict__ rout,
        const float* __restrict__ rin, const int* __restrict__ off,
        const int* __restrict__ csr, float* __restrict__ z,
        __nv_bfloat16* __restrict__ zh, int n)
{
    int gid = blockIdx.x * blockDim.x + threadIdx.x;
    int v = gid >> 5;
    if (v >= n) return;
    int lane = (gid & 31) << 2;
    int j = off[v], jend = off[v + 1];
    float ax = 0.f, ay = 0.f, az = 0.f, aw = 0.f;
    for (; j + 4 <= jend; j += 4) {
        int s0 = csr[j], s1 = csr[j + 1], s2 = csr[j + 2], s3 = csr[j + 3];
        float r0 = __ldg(rout + s0), r1 = __ldg(rout + s1);
        float r2 = __ldg(rout + s2), r3 = __ldg(rout + s3);
        float4 h0 = *(const float4*)(h + (size_t)s0 * DD + lane);
        float4 h1 = *(const float4*)(h + (size_t)s1 * DD + lane);
        float4 h2 = *(const float4*)(h + (size_t)s2 * DD + lane);
        float4 h3 = *(const float4*)(h + (size_t)s3 * DD + lane);
        ax += h0.x * r0 + h1.x * r1 + h2.x * r2 + h3.x * r3;
        ay += h0.y * r0 + h1.y * r1 + h2.y * r2 + h3.y * r3;
        az += h0.z * r0 + h1.z * r1 + h2.z * r2 + h3.z * r3;
        aw += h0.w * r0 + h1.w * r1 + h2.w * r2 + h3.w * r3;
    }
    for (; j < jend; j++) {
        int s = csr[j];
        float r = __ldg(rout + s);
        float4 hv = *(const float4*)(h + (size_t)s * DD + lane);
        ax = fmaf(hv.x, r, ax); ay = fmaf(hv.y, r, ay);
        az = fmaf(hv.z, r, az); aw = fmaf(hv.w, r, aw);
    }
    float ri = rin[v];
    float4 o;
    o.x = ax * ri; o.y = ay * ri; o.z = az * ri; o.w = aw * ri;
    *(float4*)(z + (size_t)v * DD + lane) = o;
    if (zh) {
        __nv_bfloat162 p0 = __floats2bfloat162_rn(o.x, o.y);
        __nv_bfloat162 p1 = __floats2bfloat162_rn(o.z, o.w);
        uint2 w;
        w.x = *(uint32_t*)&p0;
        w.y = *(uint32_t*)&p1;
        *(uint2*)(zh + (size_t)v * DD + lane) = w;
    }
}

// ------------- semantic attention via tensor cores --------------------------
__global__ void __launch_bounds__(256) k_att2(
        const __nv_bfloat16* __restrict__ zh_all,
        const __nv_bfloat16* __restrict__ w1h,
        const float* __restrict__ b1, float* __restrict__ attsum, int n)
{
    extern __shared__ __nv_bfloat16 smh[];
    __nv_bfloat16* As = smh;
    __nv_bfloat16* Bs = smh + 128 * SST;
    __shared__ float sred[DD];
    int t = threadIdx.x;
    int path = blockIdx.x / ATT_BLOCKS;
    int blk = blockIdx.x % ATT_BLOCKS;
    const __nv_bfloat16* zh = zh_all + (size_t)path * NU * DD;
    float* att = attsum + path * DD;
    int row0 = blk * 128;
    if (t < DD) sred[t] = 0.f;
    for (int i = t; i < 2048; i += 256) {
        int r = i >> 4, c = i & 15;
        uint4 v = make_uint4(0, 0, 0, 0);
        if (row0 + r < n) v = *(const uint4*)(zh + (size_t)(row0 + r) * DD + c * 8);
        *(uint4*)(As + r * SST + c * 8) = v;
        *(uint4*)(Bs + r * SST + c * 8) = *(const uint4*)(w1h + (size_t)r * DD + c * 8);
    }
    __syncthreads();
    int warp = t >> 5, lane = t & 31;
    int wm = warp >> 1, wn = warp & 1;
    float acc[2][8][4] = {};
    uint32_t a_base = smem_u32(As + (wm * 32 + (lane & 15)) * SST + (lane >> 4) * 8);
    uint32_t b_base = smem_u32(Bs + (wn * 64 + (lane >> 4) * 8 + (lane & 7)) * SST +
                               ((lane >> 3) & 1) * 8);
#pragma unroll
    for (int ks = 0; ks < 8; ks++) {
        uint32_t a[2][4], b[4][4];
        ldmx4(a[0], a_base + ks * 32);
        ldmx4(a[1], a_base + 16 * SST * 2 + ks * 32);
#pragma unroll
        for (int p = 0; p < 4; p++)
            ldmx4(b[p], b_base + p * 16 * SST * 2 + ks * 32);
#pragma unroll
        for (int mi = 0; mi < 2; mi++)
#pragma unroll
            for (int nt = 0; nt < 8; nt++)
                mma_bf16(acc[mi][nt], a[mi], &b[nt >> 1][(nt & 1) * 2]);
    }
    float b1v[8][2];
#pragma unroll
    for (int nt = 0; nt < 8; nt++) {
        int col = wn * 64 + nt * 8 + 2 * (lane & 3);
        b1v[nt][0] = __ldg(b1 + col);
        b1v[nt][1] = __ldg(b1 + col + 1);
    }
    float cs[8][2] = {};
    int r_lo = row0 + wm * 32 + (lane >> 2);
#pragma unroll
    for (int mi = 0; mi < 2; mi++) {
        int ra = r_lo + mi * 16, rb = ra + 8;
        bool va = ra < n, vb = rb < n;
#pragma unroll
        for (int nt = 0; nt < 8; nt++) {
            if (va) {
                cs[nt][0] += tanhf(acc[mi][nt][0] + b1v[nt][0]);
                cs[nt][1] += tanhf(acc[mi][nt][1] + b1v[nt][1]);
            }
            if (vb) {
                cs[nt][0] += tanhf(acc[mi][nt][2] + b1v[nt][0]);
                cs[nt][1] += tanhf(acc[mi][nt][3] + b1v[nt][1]);
            }
        }
    }
#pragma unroll
    for (int o = 4; o <= 16; o <<= 1)
#pragma unroll
        for (int nt = 0; nt < 8; nt++) {
            cs[nt][0] += __shfl_xor_sync(0xffffffffu, cs[nt][0], o);
            cs[nt][1] += __shfl_xor_sync(0xffffffffu, cs[nt][1], o);
        }
    if (lane < 4) {
#pragma unroll
        for (int nt = 0; nt < 8; nt++) {
            int col = wn * 64 + nt * 8 + 2 * lane;
            atomicAdd(&sred[col], cs[nt][0]);
            atomicAdd(&sred[col + 1], cs[nt][1]);
        }
    }
    __syncthreads();
    if (t < DD) atomicAdd(&att[t], sred[t]);
}

__global__ void k_beta(const float* __restrict__ W2, int n) {
    float w0 = 0.f, w1 = 0.f;
    for (int k = 0; k < DD; k++) {
        w0 += d_att[k] * W2[k];
        w1 += d_att[DD + k] * W2[k];
    }
    float inv = 1.f / (float)n;
    w0 *= inv; w1 *= inv;
    float m = fmaxf(w0, w1);
    float e0 = expf(w0 - m), e1 = expf(w1 - m);
    float den = 1.f / (e0 + e1);
    d_beta[0] = e0 * den;
    d_beta[1] = e1 * den;
}

__global__ void k_combine(const float* __restrict__ z, float* __restrict__ h, int n) {
    int i = blockIdx.x * blockDim.x + threadIdx.x;
    if (i < n) h[i] = d_beta[0] * z[i] + d_beta[1] * z[i + NU * DD];
}

__global__ void k_emb(const float* __restrict__ xf, int n) {
    int i = blockIdx.x * blockDim.x + threadIdx.x;
    if (i < n) {
        d_emb[i]           = 0.5f * (d_h[i] + xf[i]);
        d_emb[NU * DD + i] = 0.5f * (d_h[NU * DD + i] + xf[NU * DD + i]);
    }
}

// ------------------------- SSL ----------------------------------------------
__global__ void __launch_bounds__(256) k_norm(
        const float* __restrict__ e1b, const float* __restrict__ e2b,
        const int* __restrict__ idx, int slot)
{
    int gid = blockIdx.x * blockDim.x + threadIdx.x;
    int r = gid >> 5;
    if (r >= BSZ) return;
    int lane = gid & 31;
    int row = idx[r];
    float4 a = *(const float4*)(e1b + (size_t)row * DD + lane * 4);
    float4 b = *(const float4*)(e2b + (size_t)row * DD + lane * 4);
    float s11 = a.x * a.x + a.y * a.y + a.z * a.z + a.w * a.w;
    float s22 = b.x * b.x + b.y * b.y + b.z * b.z + b.w * b.w;
    float s12 = a.x * b.x + a.y * b.y + a.z * b.z + a.w * b.w;
    for (int o = 16; o; o >>= 1) {
        s11 += __shfl_xor_sync(0xffffffffu, s11, o);
        s22 += __shfl_xor_sync(0xffffffffu, s22, o);
        s12 += __shfl_xor_sync(0xffffffffu, s12, o);
    }
    float i1 = 1.f / fmaxf(sqrtf(s11), 1e-12f);
    float i2 = 1.f / fmaxf(sqrtf(s22), 1e-12f);
    if (lane == 0) d_dpos[slot * BSZ + r] = s12 * i1 * i2;
    __nv_bfloat162 na0 = __floats2bfloat162_rn(a.x * i1, a.y * i1);
    __nv_bfloat162 na1 = __floats2bfloat162_rn(a.z * i1, a.w * i1);
    __nv_bfloat162 nb0 = __floats2bfloat162_rn(b.x * i2, b.y * i2);
    __nv_bfloat162 nb1 = __floats2bfloat162_rn(b.z * i2, b.w * i2);
    uint2 wa, wb;
    wa.x = *(uint32_t*)&na0; wa.y = *(uint32_t*)&na1;
    wb.x = *(uint32_t*)&nb0; wb.y = *(uint32_t*)&nb1;
    size_t base = (size_t)slot * BSZ * DD + (size_t)r * DD + lane * 4;
    *(uint2*)(d_n1h + base) = wa;
    *(uint2*)(d_n2h + base) = wb;
}

__device__ __forceinline__ float fast_exp(float x) {
    float y = x * 1.4426950408889634f;
    float nf = rintf(y);
    float f = y - nf;
    float p = 1.5403530e-4f;
    p = fmaf(p, f, 1.3333558e-3f);
    p = fmaf(p, f, 9.6181291e-3f);
    p = fmaf(p, f, 5.5504109e-2f);
    p = fmaf(p, f, 2.4022651e-1f);
    p = fmaf(p, f, 6.9314718e-1f);
    p = fmaf(p, f, 1.0f);
    return p * __int_as_float(((int)nf + 127) << 23);
}

__global__ void __launch_bounds__(256) k_sslgemm_mma()
{
    extern __shared__ __nv_bfloat16 smh[];
    __nv_bfloat16* As = smh;
    __nv_bfloat16* Bs = smh + 128 * SST;
    __shared__ float sred[128];
    int t = threadIdx.x;
    int slot = blockIdx.z;
    int rowA0 = blockIdx.y * 128, colB0 = blockIdx.x * 128;
    const __nv_bfloat16* n1 = d_n1h + (size_t)slot * BSZ * DD;
    const __nv_bfloat16* n2 = d_n2h + (size_t)slot * BSZ * DD;
    if (t < 128) sred[t] = 0.f;
    for (int i = t; i < 2048; i += 256) {
        int r = i >> 4, c = i & 15;
        *(uint4*)(As + r * SST + c * 8) = *(const uint4*)(n1 + (size_t)(rowA0 + r) * DD + c * 8);
        *(uint4*)(Bs + r * SST + c * 8) = *(const uint4*)(n2 + (size_t)(colB0 + r) * DD + c * 8);
    }
    __syncthreads();
    int warp = t >> 5, lane = t & 31;
    int wm = warp >> 1, wn = warp & 1;
    float acc[2][8][4] = {};
    uint32_t a_base = smem_u32(As + (wm * 32 + (lane & 15)) * SST + (lane >> 4) * 8);
    uint32_t b_base = smem_u32(Bs + (wn * 64 + (lane >> 4) * 8 + (lane & 7)) * SST +
                               ((lane >> 3) & 1) * 8);
#pragma unroll
    for (int ks = 0; ks < 8; ks++) {
        uint32_t a[2][4], b[4][4];
        ldmx4(a[0], a_base + ks * 32);
        ldmx4(a[1], a_base + 16 * SST * 2 + ks * 32);
#pragma unroll
        for (int p = 0; p < 4; p++)
            ldmx4(b[p], b_base + p * 16 * SST * 2 + ks * 32);
#pragma unroll
        for (int mi = 0; mi < 2; mi++)
#pragma unroll
            for (int nt = 0; nt < 8; nt++)
                mma_bf16(acc[mi][nt], a[mi], &b[nt >> 1][(nt & 1) * 2]);
    }
    float rs[2][2] = {};
#pragma unroll
    for (int mi = 0; mi < 2; mi++)
#pragma unroll
        for (int nt = 0; nt < 8; nt++) {
            rs[mi][0] += fast_exp(2.f * acc[mi][nt][0]) + fast_exp(2.f * acc[mi][nt][1]);
            rs[mi][1] += fast_exp(2.f * acc[mi][nt][2]) + fast_exp(2.f * acc[mi][nt][3]);
        }
#pragma unroll
    for (int o = 1; o <= 2; o <<= 1) {
        rs[0][0] += __shfl_xor_sync(0xffffffffu, rs[0][0], o);
        rs[0][1] += __shfl_xor_sync(0xffffffffu, rs[0][1], o);
        rs[1][0] += __shfl_xor_sync(0xffffffffu, rs[1][0], o);
        rs[1][1] += __shfl_xor_sync(0xffffffffu, rs[1][1], o);
    }
    if ((lane & 3) == 0) {
        int r0 = wm * 32 + (lane >> 2);
        atomicAdd(&sred[r0],      rs[0][0]);
        atomicAdd(&sred[r0 + 8],  rs[0][1]);
        atomicAdd(&sred[r0 + 16], rs[1][0]);
        atomicAdd(&sred[r0 + 24], rs[1][1]);
    }
    __syncthreads();
    if (t < 128) atomicAdd(&d_alls[slot * BSZ + rowA0 + t], sred[t]);
}

__global__ void k_sslreduce(float scale) {
    __shared__ float sp[256];
    int t = threadIdx.x;
    float s = 0.f;
    for (int i = t; i < 2 * BSZ; i += 256)
        s += logf(d_alls[i]) - 2.f * d_dpos[i];
    sp[t] = s;
    __syncthreads();
    for (int o = 128; o; o >>= 1) {
        if (t < o) sp[t] += sp[t + o];
        __syncthreads();
    }
    if (t == 0) d_ssl[0] = sp[0] * scale;
}

__global__ void k_writeloss(float* dst) { *dst = d_ssl[0]; }

// ------------- final: out = LN(relu(emb[idx] @ W + b)) ----------------------
__global__ void __launch_bounds__(256) k_final(
        const float* __restrict__ embb, const int* __restrict__ idx,
        const float* __restrict__ W, const float* __restrict__ bias,
        const float* __restrict__ lng, const float* __restrict__ lnb,
        float* __restrict__ outb)
{
    extern __shared__ float smf[];
    float* Ws = smf;
    float* Zs = smf + 16384;
    int t = threadIdx.x;
    for (int i = t; i < 4096; i += 256)
        ((float4*)Ws)[i] = ((const float4*)W)[i];
    __syncthreads();
    int warp = t >> 5, lane = t & 31;
    int base = (blockIdx.x * 8 + warp) * 4;
    float* zr = Zs + warp * 512;
    for (int i = lane; i < 128; i += 32) {
        int r = i >> 5, c = i & 31;
        ((float4*)zr)[i] = ((const float4*)(embb + (size_t)idx[base + r] * DD))[c];
    }
    __syncwarp();
    float4 bb = ((const float4*)bias)[lane];
    float acc[4][4];
#pragma unroll
    for (int r = 0; r < 4; r++) {
        acc[r][0] = bb.x; acc[r][1] = bb.y; acc[r][2] = bb.z; acc[r][3] = bb.w;
    }
#pragma unroll 4
    for (int k = 0; k < DD; k++) {
        float4 w = *(const float4*)(Ws + k * DD + lane * 4);
        float zv[4];
        zv[0] = zr[k]; zv[1] = zr[DD + k]; zv[2] = zr[2 * DD + k]; zv[3] = zr[3 * DD + k];
#pragma unroll
        for (int r = 0; r < 4; r++) {
            acc[r][0] = fmaf(zv[r], w.x, acc[r][0]);
            acc[r][1] = fmaf(zv[r], w.y, acc[r][1]);
            acc[r][2] = fmaf(zv[r], w.z, acc[r][2]);
            acc[r][3] = fmaf(zv[r], w.w, acc[r][3]);
        }
    }
    float4 g4 = ((const float4*)lng)[lane];
    float4 lb4 = ((const float4*)lnb)[lane];
#pragma unroll
    for (int r = 0; r < 4; r++) {
        float v0 = fmaxf(acc[r][0], 0.f), v1 = fmaxf(acc[r][1], 0.f);
        float v2 = fmaxf(acc[r][2], 0.f), v3 = fmaxf(acc[r][3], 0.f);
        float s = v0 + v1 + v2 + v3;
        for (int o = 16; o; o >>= 1) s += __shfl_xor_sync(0xffffffffu, s, o);
        float mu = s * (1.f / 128.f);
        float w0 = v0 - mu, w1 = v1 - mu, w2 = v2 - mu, w3 = v3 - mu;
        float q = w0 * w0 + w1 * w1 + w2 * w2 + w3 * w3;
        for (int o = 16; o; o >>= 1) q += __shfl_xor_sync(0xffffffffu, q, o);
        float inv = rsqrtf(q * (1.f / 128.f) + 1e-5f);
        float4 ov;
        ov.x = w0 * inv * g4.x + lb4.x;
        ov.y = w1 * inv * g4.y + lb4.y;
        ov.z = w2 * inv * g4.z + lb4.z;
        ov.w = w3 * inv * g4.w + lb4.w;
        *(float4*)(outb + (size_t)(base + r) * DD + lane * 4) = ov;
    }
}

// ------------------------- host orchestration -------------------------------
extern "C" void kernel_launch(void* const* d_in, const int* in_sizes, int n_in,
                              void* d_out, int out_size)
{
    const float* feat_user = (const float*)d_in[0];
    const float* feat_item = (const float*)d_in[1];
    const float* u_W1 = (const float*)d_in[2];
    const float* u_b1 = (const float*)d_in[3];
    const float* u_W2 = (const float*)d_in[4];
    const float* i_W1 = (const float*)d_in[5];
    const float* i_b1 = (const float*)d_in[6];
    const float* i_W2 = (const float*)d_in[7];
    const float* user_W = (const float*)d_in[8];
    const float* user_b = (const float*)d_in[9];
    const float* item_W = (const float*)d_in[10];
    const float* item_b = (const float*)d_in[11];
    const float* ln_g = (const float*)d_in[12];
    const float* ln_b = (const float*)d_in[13];
    const int* mpsrc[4] = {(const int*)d_in[14], (const int*)d_in[16],
                           (const int*)d_in[18], (const int*)d_in[20]};
    const int* mpdst[4] = {(const int*)d_in[15], (const int*)d_in[17],
                           (const int*)d_in[19], (const int*)d_in[21]};
    const int* ui_row = (const int*)d_in[22];
    const int* ui_col = (const int*)d_in[23];
    const int* user_idx = (const int*)d_in[24];
    const int* item_idx = (const int*)d_in[25];
    const int* neg_idx = (const int*)d_in[26];
    float* out = (float*)d_out;

    float *p_h, *p_z, *p_x, *p_emb, *p_rout, *p_rin, *p_dinv, *p_att, *p_alls;
    int *p_deg, *p_off, *p_cur, *p_csr, *p_cntui, *p_offui, *p_curui, *p_csrui;
    __nv_bfloat16 *p_zh, *p_w1h;
    cudaGetSymbolAddress((void**)&p_h, d_h);
    cudaGetSymbolAddress((void**)&p_z, d_z);
    cudaGetSymbolAddress((void**)&p_zh, d_zh);
    cudaGetSymbolAddress((void**)&p_w1h, d_w1h);
    cudaGetSymbolAddress((void**)&p_x, d_x);
    cudaGetSymbolAddress((void**)&p_emb, d_emb);
    cudaGetSymbolAddress((void**)&p_rout, d_rout);
    cudaGetSymbolAddress((void**)&p_rin, d_rin);
    cudaGetSymbolAddress((void**)&p_dinv, d_dinv);
    cudaGetSymbolAddress((void**)&p_att, d_att);
    cudaGetSymbolAddress((void**)&p_alls, d_alls);
    cudaGetSymbolAddress((void**)&p_deg, d_deg);
    cudaGetSymbolAddress((void**)&p_off, d_off);
    cudaGetSymbolAddress((void**)&p_cur, d_cur);
    cudaGetSymbolAddress((void**)&p_csr, d_csr);
    cudaGetSymbolAddress((void**)&p_cntui, d_cntui);
    cudaGetSymbolAddress((void**)&p_offui, d_offui);
    cudaGetSymbolAddress((void**)&p_curui, d_curui);
    cudaGetSymbolAddress((void**)&p_csrui, d_csrui);

    const int T = 256;
    const int GEMM_SMEM = 2 * 128 * SST * 2;
    cudaFuncSetAttribute(k_att2, cudaFuncAttributeMaxDynamicSharedMemorySize, GEMM_SMEM);
    cudaFuncSetAttribute(k_sslgemm_mma, cudaFuncAttributeMaxDynamicSharedMemorySize, GEMM_SMEM);
    cudaFuncSetAttribute(k_final, cudaFuncAttributeMaxDynamicSharedMemorySize, 81920);

    // ---- degrees + CSR build ----
    k_zero_i<<<(8 * NU + T - 1) / T, T>>>(p_deg, 8 * NU);
    k_zero_i<<<(NTOT + T - 1) / T, T>>>(p_cntui, NTOT);
    for (int p = 0; p < 4; p++) {
        k_count<<<(EMP + T - 1) / T, T>>>(mpsrc[p], EMP, p_deg + p * NU);
        k_count<<<(EMP + T - 1) / T, T>>>(mpdst[p], EMP, p_deg + (4 + p) * NU);
    }
    k_count<<<(EUI + T - 1) / T, T>>>(ui_row, EUI, p_cntui);
    k_rsq<<<(4 * NU + T - 1) / T, T>>>(p_deg, p_rout, 4 * NU);
    k_rsq<<<(4 * NU + T - 1) / T, T>>>(p_deg + 4 * NU, p_rin, 4 * NU);
    k_dinvk<<<(NTOT + T - 1) / T, T>>>(p_cntui, p_dinv, NTOT);
    for (int p = 0; p < 4; p++) {
        k_scan<<<1, 1024>>>(p_deg + (4 + p) * NU, p_off + p * (NU + 1), p_cur + p * NU, NU);
        k_fill<<<(EMP + T - 1) / T, T>>>(mpdst[p], mpsrc[p], EMP, p_cur + p * NU,
                                         p_csr + (size_t)p * EMP);
    }
    k_scan<<<1, 1024>>>(p_cntui, p_offui, p_curui, NTOT);
    k_fill<<<(EUI + T - 1) / T, T>>>(ui_row, ui_col, EUI, p_curui, p_csrui);

    // ---- HAN (both sides) ----
    for (int side = 0; side < 2; side++) {
        const float* feat = side ? feat_item : feat_user;
        const float* W1 = side ? i_W1 : u_W1;
        const float* b1 = side ? i_b1 : u_b1;
        const float* W2 = side ? i_W2 : u_W2;
        float* h = p_h + (size_t)side * NU * DD;
        int p0 = side * 2, p1 = side * 2 + 1;
        k_cvtW<<<(DD * DD + T - 1) / T, T>>>(W1, p_w1h);
        for (int layer = 0; layer < 3; layer++) {
            const float* hin = layer ? h : feat;
            k_pull<<<(NU * 32) / T, T>>>(hin, p_rout + p0 * NU, p_rin + p0 * NU,
                                         p_off + p0 * (NU + 1), p_csr + (size_t)p0 * EMP,
                                         p_z, p_zh, NU);
            k_pull<<<(NU * 32) / T, T>>>(hin, p_rout + p1 * NU, p_rin + p1 * NU,
                                         p_off + p1 * (NU + 1), p_csr + (size_t)p1 * EMP,
                                         p_z + (size_t)NU * DD, p_zh + (size_t)NU * DD, NU);
            k_zero_f<<<1, 256>>>(p_att, 2 * DD);
            k_att2<<<2 * ATT_BLOCKS, 256, GEMM_SMEM>>>(p_zh, p_w1h, b1, p_att, NU);
            k_beta<<<1, 1>>>(W2, NU);
            k_combine<<<(NU * DD + T - 1) / T, T>>>(p_z, h, NU * DD);
        }
    }

    // ---- LightGCN (3 hops) ----
    cudaMemcpyAsync(p_x, feat_user, (size_t)NU * DD * sizeof(float),
                    cudaMemcpyDeviceToDevice);
    cudaMemcpyAsync(p_x + (size_t)NU * DD, feat_item, (size_t)NU * DD * sizeof(float),
                    cudaMemcpyDeviceToDevice);
    float* x0 = p_x;
    float* x1 = p_x + (size_t)NTOT * DD;
    k_pull<<<(NTOT * 32) / T, T>>>(x0, p_dinv, p_dinv, p_offui, p_csrui, x1,
                                   (__nv_bfloat16*)0, NTOT);
    k_pull<<<(NTOT * 32) / T, T>>>(x1, p_dinv, p_dinv, p_offui, p_csrui, x0,
                                   (__nv_bfloat16*)0, NTOT);
    k_pull<<<(NTOT * 32) / T, T>>>(x0, p_dinv, p_dinv, p_offui, p_csrui, x1,
                                   (__nv_bfloat16*)0, NTOT);
    float* xf = x1;

    // ---- combine embeddings ----
    k_emb<<<(NU * DD + T - 1) / T, T>>>(xf, NU * DD);

    // ---- SSL: both slots in one GEMM launch ----
    k_norm<<<(BSZ * 32) / T, T>>>(xf, p_emb, user_idx, 0);
    k_norm<<<(BSZ * 32) / T, T>>>(xf + (size_t)NU * DD, p_emb + (size_t)NU * DD, item_idx, 1);
    k_zero_f<<<(2 * BSZ + T - 1) / T, T>>>(p_alls, 2 * BSZ);
    dim3 gg(BSZ / 128, BSZ / 128, 2);
    k_sslgemm_mma<<<gg, 256, GEMM_SMEM>>>();
    k_sslreduce<<<1, 256>>>(0.4f / (float)BSZ);
    k_writeloss<<<1, 1>>>(out + (size_t)3 * BSZ * DD);

    // ---- final gather + GEMM + relu + layernorm ----
    k_final<<<BSZ / 32, 256, 81920>>>(p_emb, user_idx, user_W, user_b, ln_g, ln_b, out);
    k_final<<<BSZ / 32, 256, 81920>>>(p_emb + (size_t)NU * DD, item_idx, item_W, item_b,
                                      ln_g, ln_b, out + (size_t)BSZ * DD);
    k_final<<<BSZ / 32, 256, 81920>>>(p_emb + (size_t)NU * DD, neg_idx, item_W, item_b,
                                      ln_g, ln_b, out + (size_t)2 * BSZ * DD);
}